// round 13
// baseline (speedup 1.0000x reference)
#include <cuda_runtime.h>
#include <cstdint>

// DocREDModel: entity-pool -> tanh-projection -> block-bilinear classifier
// B=16 S=2048 H=768 E=32 M=4 P=128 L=97 BLOCK=64
//
// Factorized pipeline:
//   C[e2, k1, l]  = sum_j zt[e2, cb*64+j] * Wc[k1*64+j, l]       (4.8 GF)
//   C96[e2, k1]   = sum_j zt[e2, cb*64+j] * w96[k1*64+j]
//   Dp[z][b,e1,e2,l] = partial over k-quarter z of zh @ C        (2.4 GF)
//   D96[b,e1,e2]  = zh . C96
//   out[n, l]     = (l<96 ? sum_z Dp[z][...] : D96[...]) + bc[l]
// stage1 v4: thread tile 8e2 x 8l -> smem traffic 1.0 B/MAC (crossbar = FMA peak).

#define B_    16
#define S_    2048
#define H_    768
#define E_    32
#define L_    97
#define CH    96
#define NROWS 2048
#define NENT  512
#define KTOT  49152
#define DPBLK (B_ * E_ * E_ * CH)

typedef unsigned long long ull;

__device__ float g_ent[NENT * H_];
__device__ float g_zh[NENT * H_];
__device__ float g_zt[NENT * H_];
__device__ float g_w96[KTOT];
__device__ float g_C[(size_t)NENT * H_ * CH];      // 151 MB scratch
__device__ float g_C96[NENT * H_];
__device__ float g_Dp[4 * DPBLK];                  // 25 MB partials
__device__ float g_D96[B_ * E_ * E_];

__device__ __forceinline__ ull ffma2(ull a, ull b, ull c) {
    ull d; asm("fma.rn.f32x2 %0, %1, %2, %3;" : "=l"(d) : "l"(a), "l"(b), "l"(c));
    return d;
}
__device__ __forceinline__ ull fsplat(float x) {
    ull d; asm("mov.b64 %0, {%1, %1};" : "=l"(d) : "f"(x));
    return d;
}
__device__ __forceinline__ float lo32(ull v) { return __uint_as_float((unsigned)(v & 0xffffffffull)); }
__device__ __forceinline__ float hi32(ull v) { return __uint_as_float((unsigned)(v >> 32)); }
__device__ __forceinline__ void cp16(uint32_t dst, const void* src) {
    asm volatile("cp.async.cg.shared.global [%0], [%1], 16;" :: "r"(dst), "l"(src));
}

// ---------------------------------------------------------------- kernel 1
__global__ void build_ent_kernel(const float* __restrict__ feats,
                                 const int* __restrict__ pos) {
    int be = blockIdx.x;
    int b  = be >> 5;
    const int* pp = pos + be * 4;
    int p0 = pp[0], p1 = pp[1], p2 = pp[2], p3 = pp[3];
    float w1 = (p1 != p0) ? 1.f : 0.f;
    float w2 = (p2 != p0 && p2 != p1) ? 1.f : 0.f;
    float w3 = (p3 != p0 && p3 != p1 && p3 != p2) ? 1.f : 0.f;
    const float* base = feats + (size_t)b * S_ * H_;
    const float4* r0 = (const float4*)(base + (size_t)p0 * H_);
    const float4* r1 = (const float4*)(base + (size_t)p1 * H_);
    const float4* r2 = (const float4*)(base + (size_t)p2 * H_);
    const float4* r3 = (const float4*)(base + (size_t)p3 * H_);
    int t = threadIdx.x;   // 192 threads * float4 = 768
    float4 v0 = r0[t], v1 = r1[t], v2 = r2[t], v3 = r3[t];
    float4 o;
    o.x = v0.x + w1 * v1.x + w2 * v2.x + w3 * v3.x;
    o.y = v0.y + w1 * v1.y + w2 * v2.y + w3 * v3.y;
    o.z = v0.z + w1 * v1.z + w2 * v2.z + w3 * v3.z;
    o.w = v0.w + w1 * v1.w + w2 * v2.w + w3 * v3.w;
    ((float4*)(g_ent + (size_t)be * H_))[t] = o;
}

// ---------------------------------------------------------------- kernel 2
__global__ void __launch_bounds__(256)
gemm_tanh_kernel(const float* __restrict__ Wh, const float* __restrict__ bh,
                 const float* __restrict__ Wt, const float* __restrict__ bt) {
    const float* W    = blockIdx.z ? Wt : Wh;
    const float* bias = blockIdx.z ? bt : bh;
    float*       Z    = blockIdx.z ? g_zt : g_zh;

    __shared__ float AsT[16 * 68];
    __shared__ float Bd[16 * 256];

    int tid = threadIdx.x;
    int mg  = tid & 15;
    int ng  = tid >> 4;
    int m0  = blockIdx.x * 64;
    int n0  = blockIdx.y * 128;

    ull acc[2][8];
#pragma unroll
    for (int p = 0; p < 2; p++)
#pragma unroll
        for (int c = 0; c < 8; c++) acc[p][c] = 0ull;

    for (int k0 = 0; k0 < H_; k0 += 16) {
        __syncthreads();
#pragma unroll
        for (int e = tid; e < 1024; e += 256) {
            int kk = e & 15, m = e >> 4;
            AsT[kk * 68 + m] = g_ent[(m0 + m) * H_ + k0 + kk];
        }
#pragma unroll
        for (int e = tid; e < 2048; e += 256) {
            int n = e & 127, kk = e >> 7;
            float w = W[(k0 + kk) * H_ + n0 + n];
            ((float2*)Bd)[kk * 128 + n] = make_float2(w, w);
        }
        __syncthreads();
#pragma unroll
        for (int kk = 0; kk < 16; kk++) {
            ulonglong2 av = *(const ulonglong2*)&AsT[kk * 68 + mg * 4];
            const ulonglong2* wp = (const ulonglong2*)&Bd[kk * 256 + ng * 16];
            ulonglong2 w01 = wp[0], w23 = wp[1], w45 = wp[2], w67 = wp[3];
            ull w[8] = {w01.x, w01.y, w23.x, w23.y, w45.x, w45.y, w67.x, w67.y};
#pragma unroll
            for (int c = 0; c < 8; c++) {
                acc[0][c] = ffma2(av.x, w[c], acc[0][c]);
                acc[1][c] = ffma2(av.y, w[c], acc[1][c]);
            }
        }
    }
#pragma unroll
    for (int p = 0; p < 2; p++) {
#pragma unroll
        for (int c = 0; c < 8; c++) {
            int n = n0 + ng * 8 + c;
            float bv = bias[n];
            int m = m0 + mg * 4 + 2 * p;
            Z[m * H_ + n]       = tanhf(lo32(acc[p][c]) + bv);
            Z[(m + 1) * H_ + n] = tanhf(hi32(acc[p][c]) + bv);
        }
    }
}

// ---------------------------------------------------------------- w96 extract
__global__ void w96_extract_kernel(const float* __restrict__ Wc) {
    int k = blockIdx.x * blockDim.x + threadIdx.x;
    if (k < KTOT) g_w96[k] = Wc[(size_t)k * L_ + 96];
}

// ---------------------------------------------------------------- stage 1 v4
// Grid (12 cb, 8 e2-tiles of 64, 32 i-pairs), 192 threads.
// Thread tile 8 e2 x 8 l (one il).  smem 66.5KB -> 3 CTA/SM.
// Per k: 4 LDS.128 + 32 FFMA2  => 1.0 B/MAC: crossbar and FMA co-saturate.
__global__ void __launch_bounds__(192)
stage1_kernel(const float* __restrict__ Wc) {
    __shared__ float As[64 * 68];      // [j][e2], stride 68   (17.4KB)
    __shared__ float Bs[64 * 192];     // [j][il*96 + l]       (48KB)

    int tid = threadIdx.x;
    int cb  = blockIdx.x;
    int e0  = blockIdx.y * 64;
    int ip  = blockIdx.z;              // i-pair 0..31

    for (int e = tid; e < 4096; e += 192) {
        int j = e & 63, m = e >> 6;
        As[j * 68 + m] = g_zt[(e0 + m) * H_ + cb * 64 + j];
    }
    for (int e = tid; e < 12288; e += 192) {
        int row = e / 96, l = e - row * 96;     // row = il*64 + j
        int il = row >> 6, j = row & 63;
        Bs[j * 192 + il * 96 + l] =
            Wc[(size_t)((cb * 64 + ip * 2 + il) * 64 + j) * L_ + l];
    }
    __syncthreads();

    int mg   = tid & 7;                // 8 e2 rows
    int rest = tid >> 3;               // 0..23
    int ng   = rest % 12;              // 8 l
    int il   = rest / 12;              // 0..1
    int l0   = ng * 8;
    const float* aptr = As + mg * 8;
    const float* bptr = Bs + il * 96 + l0;

    ull acc[8][4];
#pragma unroll
    for (int m = 0; m < 8; m++)
#pragma unroll
        for (int p = 0; p < 4; p++) acc[m][p] = 0ull;

#pragma unroll 2
    for (int k = 0; k < 64; k++) {
        float4 x0 = *(const float4*)(aptr + k * 68);
        float4 x1 = *(const float4*)(aptr + k * 68 + 4);
        ulonglong2 bA = *(const ulonglong2*)(bptr + k * 192);
        ulonglong2 bB = *(const ulonglong2*)(bptr + k * 192 + 4);
        ull bv[4] = {bA.x, bA.y, bB.x, bB.y};
        float av[8] = {x0.x, x0.y, x0.z, x0.w, x1.x, x1.y, x1.z, x1.w};
#pragma unroll
        for (int m = 0; m < 8; m++) {
            ull s = fsplat(av[m]);
            acc[m][0] = ffma2(s, bv[0], acc[m][0]);
            acc[m][1] = ffma2(s, bv[1], acc[m][1]);
            acc[m][2] = ffma2(s, bv[2], acc[m][2]);
            acc[m][3] = ffma2(s, bv[3], acc[m][3]);
        }
    }

    int k1 = cb * 64 + ip * 2 + il;
#pragma unroll
    for (int m = 0; m < 8; m++) {
        float* cptr = g_C + ((size_t)(e0 + mg * 8 + m) * H_ + k1) * CH + l0;
        *(ulonglong2*)(cptr + 0) = make_ulonglong2(acc[m][0], acc[m][1]);
        *(ulonglong2*)(cptr + 4) = make_ulonglong2(acc[m][2], acc[m][3]);
    }
}

// ---------------------------------------------------------------- c96
__global__ void __launch_bounds__(256)
c96_kernel() {
    __shared__ float zts[64 * 68];
    __shared__ float wts[64 * 64];

    int tid = threadIdx.x;
    int cb  = blockIdx.x;
    int e0  = blockIdx.y * 64;

    for (int e = tid; e < 4096; e += 256) {
        int j = e & 63, m = e >> 6;
        zts[j * 68 + m] = g_zt[(e0 + m) * H_ + cb * 64 + j];
    }
    for (int e = tid; e < 1024; e += 256)
        ((float4*)wts)[e] = ((const float4*)(g_w96 + cb * 4096))[e];
    __syncthreads();

    int mg = tid & 15;
    int i0 = (tid >> 4) * 4;

    ull acc[2][4];
#pragma unroll
    for (int p = 0; p < 2; p++)
#pragma unroll
        for (int i = 0; i < 4; i++) acc[p][i] = 0ull;

#pragma unroll 4
    for (int j = 0; j < 64; j++) {
        ulonglong2 a = *(const ulonglong2*)&zts[j * 68 + mg * 4];
#pragma unroll
        for (int i = 0; i < 4; i++) {
            ull w = fsplat(wts[(i0 + i) * 64 + j]);
            acc[0][i] = ffma2(a.x, w, acc[0][i]);
            acc[1][i] = ffma2(a.y, w, acc[1][i]);
        }
    }

#pragma unroll
    for (int p = 0; p < 2; p++) {
        int e2a = e0 + mg * 4 + 2 * p;
#pragma unroll
        for (int i = 0; i < 4; i++) {
            int k1 = cb * 64 + i0 + i;
            g_C96[e2a * H_ + k1]       = lo32(acc[p][i]);
            g_C96[(e2a + 1) * H_ + k1] = hi32(acc[p][i]);
        }
    }
}

// ---------------------------------------------------------------- stage 2
// Dp[z][b,e1,e2,l] = sum_{k in quarter z} zh[b*32+e1,k] * C[b*32+e2,k,l]
// Grid (16 b, 32 e2, 4 z), 256 threads; 3 chunks of 64 k per CTA.
#define S2_AS_F (64 * 36)
#define S2_BS_F (64 * 96)
#define S2_SMEM ((S2_AS_F + 2 * S2_BS_F) * 4)
__global__ void __launch_bounds__(256)
stage2_kernel() {
    extern __shared__ float s2[];
    float* As = s2;                    // [kk][e1], stride 36
    float* Bs = s2 + S2_AS_F;          // [2][kk][96]

    int tid = threadIdx.x;
    int b   = blockIdx.x;
    int e2  = blockIdx.y;
    int z   = blockIdx.z;
    const float* crow = g_C + (size_t)(b * E_ + e2) * H_ * CH + (size_t)(z * 192) * CH;
    const float* zrow = g_zh + (size_t)(b * E_) * H_ + z * 192;
    uint32_t bs_u = (uint32_t)__cvta_generic_to_shared(Bs);

    int mg = tid >> 4;
    int ng = tid & 15;
    int l0 = ng * 6;

    float pa[8];
#pragma unroll
    for (int s = 0; s < 8; s++) {
        int e = tid + s * 256, e1 = e >> 6, kk = e & 63;
        pa[s] = zrow[e1 * H_ + kk];
    }
#pragma unroll
    for (int s = 0; s < 6; s++) {
        int u = tid + s * 256;
        int k = u / 24, c = u - k * 24;
        cp16(bs_u + (unsigned)(k * 96 + c * 4) * 4, crow + (size_t)k * CH + c * 4);
    }
    asm volatile("cp.async.commit_group;");

    ull acc[2][3];
#pragma unroll
    for (int m = 0; m < 2; m++)
#pragma unroll
        for (int p = 0; p < 3; p++) acc[m][p] = 0ull;

    for (int kc = 0; kc < 3; kc++) {
        int buf = kc & 1;
        asm volatile("cp.async.wait_group 0;");
        __syncthreads();
#pragma unroll
        for (int s = 0; s < 8; s++) {
            int e = tid + s * 256, e1 = e >> 6, kk = e & 63;
            As[kk * 36 + e1] = pa[s];
        }
        if (kc < 2) {
            const float* cc = crow + (size_t)(kc + 1) * 64 * CH;
            uint32_t db = bs_u + (unsigned)((buf ^ 1) * S2_BS_F) * 4;
#pragma unroll
            for (int s = 0; s < 6; s++) {
                int u = tid + s * 256;
                int k = u / 24, c = u - k * 24;
                cp16(db + (unsigned)(k * 96 + c * 4) * 4, cc + (size_t)k * CH + c * 4);
            }
            asm volatile("cp.async.commit_group;");
        }
        __syncthreads();
        if (kc < 2) {
            const float* zc = zrow + (kc + 1) * 64;
#pragma unroll
            for (int s = 0; s < 8; s++) {
                int e = tid + s * 256, e1 = e >> 6, kk = e & 63;
                pa[s] = zc[e1 * H_ + kk];
            }
        }

        const float* bb = Bs + buf * S2_BS_F + l0;
#pragma unroll 4
        for (int k = 0; k < 64; k++) {
            ull a = *(const ull*)&As[k * 36 + mg * 2];
            ull s0 = fsplat(lo32(a));
            ull s1 = fsplat(hi32(a));
            ull b0 = *(const ull*)(bb + k * 96);
            ull b1 = *(const ull*)(bb + k * 96 + 2);
            ull b2 = *(const ull*)(bb + k * 96 + 4);
            acc[0][0] = ffma2(s0, b0, acc[0][0]);
            acc[1][0] = ffma2(s1, b0, acc[1][0]);
            acc[0][1] = ffma2(s0, b1, acc[0][1]);
            acc[1][1] = ffma2(s1, b1, acc[1][1]);
            acc[0][2] = ffma2(s0, b2, acc[0][2]);
            acc[1][2] = ffma2(s1, b2, acc[1][2]);
        }
    }

#pragma unroll
    for (int m = 0; m < 2; m++) {
        int e1 = mg * 2 + m;
        float* dptr = g_Dp + (size_t)z * DPBLK +
                      (size_t)((b * E_ + e1) * E_ + e2) * CH + l0;
        *(ull*)(dptr + 0) = acc[m][0];
        *(ull*)(dptr + 2) = acc[m][1];
        *(ull*)(dptr + 4) = acc[m][2];
    }
}

// ---------------------------------------------------------------- d96
__global__ void __launch_bounds__(128)
d96_kernel() {
    __shared__ float c96s[H_];
    int b  = blockIdx.x;
    int e2 = blockIdx.y;
    int tid = threadIdx.x;
    const float* crow = g_C96 + (size_t)(b * E_ + e2) * H_;
    for (int s = tid; s < H_ / 4; s += 128)
        ((float4*)c96s)[s] = ((const float4*)crow)[s];
    __syncthreads();

    int e1 = tid >> 2, q = tid & 3;
    const float* zr = g_zh + (size_t)(b * E_ + e1) * H_;
    float acc = 0.f;
#pragma unroll 8
    for (int k = q; k < H_; k += 4) acc += zr[k] * c96s[k];
    acc += __shfl_down_sync(0xffffffffu, acc, 2, 4);
    acc += __shfl_down_sync(0xffffffffu, acc, 1, 4);
    if (q == 0) g_D96[(b * E_ + e1) * E_ + e2] = acc;
}

// ---------------------------------------------------------------- gather
__global__ void gather_kernel(const int* __restrict__ ht,
                              const float* __restrict__ bc,
                              float* __restrict__ out) {
    int idx = blockIdx.x * 256 + threadIdx.x;
    if (idx >= NROWS * L_) return;
    int n = idx / L_, l = idx - n * L_;
    int b  = n >> 7;
    int e1 = ht[2 * n];
    int e2 = ht[2 * n + 1];
    size_t pe = (size_t)((b * E_ + e1) * E_ + e2);
    float v;
    if (l < CH) {
        v = g_Dp[pe * CH + l] + g_Dp[DPBLK + pe * CH + l] +
            g_Dp[2 * DPBLK + pe * CH + l] + g_Dp[3 * DPBLK + pe * CH + l];
    } else {
        v = g_D96[pe];
    }
    out[idx] = v + bc[l];
}

// ---------------------------------------------------------------- launch
extern "C" void kernel_launch(void* const* d_in, const int* in_sizes, int n_in,
                              void* d_out, int out_size) {
    const float* feats = (const float*)d_in[0];
    const int*   pos   = (const int*)d_in[1];
    const int*   ht    = (const int*)d_in[2];
    const float* Wh    = (const float*)d_in[3];
    const float* bh    = (const float*)d_in[4];
    const float* Wt    = (const float*)d_in[5];
    const float* bt    = (const float*)d_in[6];
    const float* Wc    = (const float*)d_in[7];
    const float* bc    = (const float*)d_in[8];
    float*       out   = (float*)d_out;

    cudaFuncSetAttribute(stage2_kernel,
                         cudaFuncAttributeMaxDynamicSharedMemorySize, S2_SMEM);

    build_ent_kernel<<<NENT, 192>>>(feats, pos);                  // 1

    dim3 g2(NENT / 64, H_ / 128, 2);
    gemm_tanh_kernel<<<g2, 256>>>(Wh, bh, Wt, bt);                // 2

    w96_extract_kernel<<<(KTOT + 255) / 256, 256>>>(Wc);          // 3

    dim3 g5(12, 8, 32);
    stage1_kernel<<<g5, 192>>>(Wc);                               // 4 (ncu)

    dim3 gc(12, 8);
    c96_kernel<<<gc, 256>>>();                                    // 5

    dim3 g6(B_, E_, 4);
    stage2_kernel<<<g6, 256, S2_SMEM>>>();                        // 6

    dim3 gd(B_, E_);
    d96_kernel<<<gd, 128>>>();                                    // 7

    gather_kernel<<<(NROWS * L_ + 255) / 256, 256>>>(ht, bc, out); // 8
}